// round 13
// baseline (speedup 1.0000x reference)
#include <cuda_runtime.h>
#include <cuda_fp16.h>
#include <cuda_bf16.h>
#include <cstdint>

// Problem constants
#define BATCH 8
#define CI    64
#define CO    128
#define HH    128
#define WW    128
#define HW    (HH*WW)          // 16384

// Scratch: y = conv1x1(x), PIXEL-MAJOR, fp16: y[b][p][c]. 32 MiB.
__device__ __half g_y[BATCH * HW * CO];

// ---- packed f32x2 helpers (Blackwell FFMA2) --------------------------------
__device__ __forceinline__ unsigned long long pk2(float a, float b) {
    unsigned long long r;
    asm("mov.b64 %0, {%1, %2};" : "=l"(r) : "f"(a), "f"(b));
    return r;
}
__device__ __forceinline__ void fma2(unsigned long long& d,
                                     unsigned long long a,
                                     unsigned long long b) {
    asm("fma.rn.f32x2 %0, %1, %2, %0;" : "+l"(d) : "l"(a), "l"(b));
}
__device__ __forceinline__ void upk2(float& a, float& b, unsigned long long v) {
    asm("mov.b64 {%0, %1}, %2;" : "=f"(a), "=f"(b) : "l"(v));
}

// ---- bf16 split helper ------------------------------------------------------
__device__ __forceinline__ void split_bf16(float v, uint32_t& hi, uint32_t& lo) {
    __nv_bfloat16 h = __float2bfloat16_rn(v);
    float r = v - __bfloat162float(h);
    __nv_bfloat16 l = __float2bfloat16_rn(r);
    hi = (uint32_t)__bfloat16_as_ushort(h);
    lo = (uint32_t)__bfloat16_as_ushort(l);
}

#define MMA_BF16(d, a, b0, b1)                                                  \
    asm volatile("mma.sync.aligned.m16n8k16.row.col.f32.bf16.bf16.f32 "         \
                 "{%0,%1,%2,%3}, {%4,%5,%6,%7}, {%8,%9}, {%0,%1,%2,%3};"        \
                 : "+f"((d)[0]), "+f"((d)[1]), "+f"((d)[2]), "+f"((d)[3])       \
                 : "r"((a)[0]), "r"((a)[1]), "r"((a)[2]), "r"((a)[3]),          \
                   "r"(b0), "r"(b1))

// half2-pair (4 channels) -> float4
__device__ __forceinline__ float4 h2f4(uint2 u) {
    __half2 a = *reinterpret_cast<__half2*>(&u.x);
    __half2 b = *reinterpret_cast<__half2*>(&u.y);
    float2 fa = __half22float2(a);
    float2 fb = __half22float2(b);
    return make_float4(fa.x, fa.y, fb.x, fb.y);
}
__device__ __forceinline__ float dot4(float4 a, float4 b) {
    float r = a.x * b.x;
    r = fmaf(a.y, b.y, r);
    r = fmaf(a.z, b.z, r);
    r = fmaf(a.w, b.w, r);
    return r;
}

// ---------------------------------------------------------------------------
// Kernel 1: HYBRID dual-pipe 1x1 conv. Per CTA: 128 px x 128 ch.
// Warps 0-3: FFMA2 (fma pipe) on pixels 0-63.
// Warps 4-7: bf16 3-term mma.sync (tensor pipe) on pixels 64-127.
// Smem: Ws fp32 [64][128] | Xs fp32 [64][64] | Xb uint2[64][33] | Wb uint2[128][33]
// MMA epilogue reuses Ws+Xs region (consumed by then) as fp32 stage.
// ---------------------------------------------------------------------------
#define OFF_WS 0
#define OFF_XS 32768
#define OFF_XB 49152
#define OFF_WB 66048
#define CONV_SMEM 99840
#define STG 132

__global__ void __launch_bounds__(256) conv1x1_hybrid(const float* __restrict__ x,
                                                      const float* __restrict__ Wc,
                                                      const float* __restrict__ bc)
{
    extern __shared__ char smraw[];
    float* Ws = reinterpret_cast<float*>(smraw + OFF_WS);   // [64][128]
    float* Xs = reinterpret_cast<float*>(smraw + OFF_XS);   // [64][64]
    uint2* Xb = reinterpret_cast<uint2*>(smraw + OFF_XB);   // [64][33]
    uint2* Wb = reinterpret_cast<uint2*>(smraw + OFF_WB);   // [128][33]
    float* stage = reinterpret_cast<float*>(smraw);         // alias, epilogue

    const int b   = blockIdx.y;
    const int p0  = blockIdx.x * 128;
    const int tid = threadIdx.x;
    const int wid = tid >> 5;
    const int lane = tid & 31;

    const float* xb = x + (size_t)b * CI * HW;

    // ---- Fill all operand tiles (256 threads) ----
    for (int idx = tid; idx < 64 * 128; idx += 256) {       // Ws
        int i = idx >> 7;
        int o = idx & 127;
        Ws[idx] = Wc[o * CI + i];
    }
    {
        const float4* xb4 = reinterpret_cast<const float4*>(xb);
        float4* Xs4 = reinterpret_cast<float4*>(Xs);
        for (int idx = tid; idx < 1024; idx += 256) {        // Xs (px 0-63)
            int i  = idx >> 4;
            int p4 = idx & 15;
            Xs4[idx] = xb4[i * (HW / 4) + (p0 >> 2) + p4];
        }
    }
    for (int idx = tid; idx < 2048; idx += 256) {            // Xb (px 64-127)
        int kk = idx >> 6;
        int p  = idx & 63;
        float v0 = xb[(size_t)(2 * kk) * HW + p0 + 64 + p];
        float v1 = xb[(size_t)(2 * kk + 1) * HW + p0 + 64 + p];
        uint32_t h0, l0, h1, l1;
        split_bf16(v0, h0, l0);
        split_bf16(v1, h1, l1);
        Xb[p * 33 + kk] = make_uint2(h0 | (h1 << 16), l0 | (l1 << 16));
    }
    for (int idx = tid; idx < 4096; idx += 256) {            // Wb
        int c  = idx >> 5;
        int kk = idx & 31;
        float2 w = *reinterpret_cast<const float2*>(&Wc[c * CI + 2 * kk]);
        uint32_t h0, l0, h1, l1;
        split_bf16(w.x, h0, l0);
        split_bf16(w.y, h1, l1);
        Wb[c * 33 + kk] = make_uint2(h0 | (h1 << 16), l0 | (l1 << 16));
    }
    __syncthreads();

    __half* yb = g_y + ((size_t)b * HW + p0) * CO;

    if (wid < 4) {
        // ================= FFMA2 path: pixels 0-63 =================
        const int tx = tid & 15;   // channel group
        const int ty = tid >> 4;   // pixel group (0..7), 8 px each

        unsigned long long acc2[4][8];
#pragma unroll
        for (int q = 0; q < 4; ++q)
#pragma unroll
            for (int k = 0; k < 8; ++k) acc2[q][k] = 0ull;

        const float4* Ws4 = reinterpret_cast<const float4*>(Ws);

#pragma unroll 4
        for (int i = 0; i < 64; ++i) {
            float4 w0 = Ws4[i * 32 + tx];
            float4 w1 = Ws4[i * 32 + 16 + tx];

            const float* xrow = Xs + i * 64;
            ulonglong2 xa = *reinterpret_cast<const ulonglong2*>(xrow + ty * 8);
            ulonglong2 xv = *reinterpret_cast<const ulonglong2*>(xrow + ty * 8 + 4);
            unsigned long long xp[4] = {xa.x, xa.y, xv.x, xv.y};

            unsigned long long wd[8];
            wd[0] = pk2(w0.x, w0.x); wd[1] = pk2(w0.y, w0.y);
            wd[2] = pk2(w0.z, w0.z); wd[3] = pk2(w0.w, w0.w);
            wd[4] = pk2(w1.x, w1.x); wd[5] = pk2(w1.y, w1.y);
            wd[6] = pk2(w1.z, w1.z); wd[7] = pk2(w1.w, w1.w);

#pragma unroll
            for (int q = 0; q < 4; ++q)
#pragma unroll
                for (int k = 0; k < 8; ++k)
                    fma2(acc2[q][k], xp[q], wd[k]);
        }

        float bv[8];
#pragma unroll
        for (int k = 0; k < 4; ++k) {
            bv[k]     = bc[tx * 4 + k];
            bv[k + 4] = bc[64 + tx * 4 + k];
        }

#pragma unroll
        for (int q = 0; q < 4; ++q) {
#pragma unroll
            for (int half = 0; half < 2; ++half) {
                float e[8];
#pragma unroll
                for (int k = 0; k < 8; ++k) {
                    float lo, hi;
                    upk2(lo, hi, acc2[q][k]);
                    e[k] = (half == 0 ? lo : hi) + bv[k];
                }
                __half* dst = yb + (size_t)(ty * 8 + q * 2 + half) * CO;
                __half2 h0 = __floats2half2_rn(e[0], e[1]);
                __half2 h1 = __floats2half2_rn(e[2], e[3]);
                __half2 h2 = __floats2half2_rn(e[4], e[5]);
                __half2 h3 = __floats2half2_rn(e[6], e[7]);
                *reinterpret_cast<uint2*>(dst + tx * 4) =
                    make_uint2(*reinterpret_cast<uint32_t*>(&h0),
                               *reinterpret_cast<uint32_t*>(&h1));
                *reinterpret_cast<uint2*>(dst + 64 + tx * 4) =
                    make_uint2(*reinterpret_cast<uint32_t*>(&h2),
                               *reinterpret_cast<uint32_t*>(&h3));
            }
        }
        __syncthreads();   // (1) FFMA warps done with Ws/Xs
        __syncthreads();   // (2) wait for MMA stage writes
    } else {
        // ================= MMA path: pixels 64-127 =================
        const int w   = wid - 4;          // 0..3
        const int pxr = (w & 1) * 32;     // pixel tile (relative 0/32)
        const int ch0 = (w >> 1) * 64;    // channel tile (0/64)
        const int g   = lane >> 2;
        const int t   = lane & 3;

        float acc[2][8][4];
#pragma unroll
        for (int mt = 0; mt < 2; ++mt)
#pragma unroll
            for (int nt = 0; nt < 8; ++nt)
#pragma unroll
                for (int e = 0; e < 4; ++e) acc[mt][nt][e] = 0.0f;

#pragma unroll
        for (int ks = 0; ks < 4; ++ks) {
            const int kp0 = ks * 8;

            uint32_t ah[2][4], al[2][4];
#pragma unroll
            for (int mt = 0; mt < 2; ++mt) {
                const int r0 = pxr + mt * 16 + g;
                uint2 A0 = Xb[r0 * 33 + kp0 + t];
                uint2 A1 = Xb[(r0 + 8) * 33 + kp0 + t];
                uint2 A2 = Xb[r0 * 33 + kp0 + 4 + t];
                uint2 A3 = Xb[(r0 + 8) * 33 + kp0 + 4 + t];
                ah[mt][0] = A0.x; ah[mt][1] = A1.x; ah[mt][2] = A2.x; ah[mt][3] = A3.x;
                al[mt][0] = A0.y; al[mt][1] = A1.y; al[mt][2] = A2.y; al[mt][3] = A3.y;
            }

#pragma unroll
            for (int nt = 0; nt < 8; ++nt) {
                const int c = ch0 + nt * 8 + g;
                uint2 B0 = Wb[c * 33 + kp0 + t];
                uint2 B1 = Wb[c * 33 + kp0 + 4 + t];
#pragma unroll
                for (int mt = 0; mt < 2; ++mt) {
                    MMA_BF16(acc[mt][nt], ah[mt], B0.x, B1.x);  // xh*Wh
                    MMA_BF16(acc[mt][nt], ah[mt], B0.y, B1.y);  // xh*Wl
                    MMA_BF16(acc[mt][nt], al[mt], B0.x, B1.x);  // xl*Wh
                }
            }
        }

        __syncthreads();   // (1) FFMA warps finished reading Ws/Xs

        // Scatter accumulators to stage[p_rel][c] (stride STG)
#pragma unroll
        for (int mt = 0; mt < 2; ++mt) {
#pragma unroll
            for (int nt = 0; nt < 8; ++nt) {
                int p = pxr + mt * 16 + g;
                int c = ch0 + nt * 8 + 2 * t;
                *reinterpret_cast<float2*>(&stage[p * STG + c]) =
                    make_float2(acc[mt][nt][0], acc[mt][nt][1]);
                *reinterpret_cast<float2*>(&stage[(p + 8) * STG + c]) =
                    make_float2(acc[mt][nt][2], acc[mt][nt][3]);
            }
        }
        __syncthreads();   // (2) stage ready
    }

    // Cooperative epilogue for MMA half: bias + fp16 stores (px 64-127)
#pragma unroll
    for (int j = 0; j < 8; ++j) {
        int fidx = tid + 256 * j;    // 0..2047 float4 tasks
        int p  = fidx >> 5;          // 0..63 (relative)
        int cq = fidx & 31;
        float4 v  = *reinterpret_cast<const float4*>(&stage[p * STG + cq * 4]);
        float4 bb = *reinterpret_cast<const float4*>(&bc[cq * 4]);
        __half2 h0 = __floats2half2_rn(v.x + bb.x, v.y + bb.y);
        __half2 h1 = __floats2half2_rn(v.z + bb.z, v.w + bb.w);
        *reinterpret_cast<uint2*>(yb + (size_t)(64 + p) * CO + cq * 4) =
            make_uint2(*reinterpret_cast<uint32_t*>(&h0),
                       *reinterpret_cast<uint32_t*>(&h1));
    }
}

// ---------------------------------------------------------------------------
// Kernel 2: 3x3 local attention, warp per 2x2 pixel block (R12, best known).
// ---------------------------------------------------------------------------
__global__ void __launch_bounds__(256, 3) attn3x3_kernel(float* __restrict__ out)
{
    __shared__ float so[32 * CO];        // [px(row*16+col)][c]  16KB
    __shared__ float wsm[8][4][12];      // [warp][pixel][9 weights]

    const int tid  = threadIdx.x;
    const int wid  = tid >> 5;
    const int lane = tid & 31;

    const int b  = blockIdx.z;
    const int r0 = blockIdx.y * 2;
    const int wc = blockIdx.x * 16;
    const int c0 = wc + wid * 2;

    const __half* ybase = g_y + ((size_t)b * HW) * CO + lane * 4;

    uint2 vh[4][4];
#pragma unroll
    for (int r = 0; r < 4; ++r) {
        int gh = r0 - 1 + r;
#pragma unroll
        for (int c = 0; c < 4; ++c) {
            int gw = c0 - 1 + c;
            if ((unsigned)gh < HH && (unsigned)gw < WW) {
                vh[r][c] = *reinterpret_cast<const uint2*>(
                    ybase + (size_t)(gh * WW + gw) * CO);
            } else {
                vh[r][c] = make_uint2(0u, 0u);
            }
        }
    }

    const float scale = 0.08838834764831845f; // 1/sqrt(128)
    const bool loHalf = lane < 16;
    const int  q8     = (lane >> 3) & 3;

    const float4 mA = h2f4(vh[1][1]);
    const float4 mB = h2f4(vh[1][2]);
    const float4 mC = h2f4(vh[2][1]);
    const float4 mD = h2f4(vh[2][2]);

    float s[9];
#pragma unroll
    for (int n = 0; n < 9; ++n) {
        const int di = n / 3, dj = n % 3;
        float sA = dot4(h2f4(vh[di][dj]),         mA);
        float sB = dot4(h2f4(vh[di][dj + 1]),     mB);
        float sC = dot4(h2f4(vh[di + 1][dj]),     mC);
        float sD = dot4(h2f4(vh[di + 1][dj + 1]), mD);
        float fA = sA + __shfl_xor_sync(0xffffffffu, sA, 16);
        float fB = sB + __shfl_xor_sync(0xffffffffu, sB, 16);
        float fC = sC + __shfl_xor_sync(0xffffffffu, sC, 16);
        float fD = sD + __shfl_xor_sync(0xffffffffu, sD, 16);
        float sLo = loHalf ? fA : fC;
        float sHi = loHalf ? fB : fD;
        float gLo = sLo + __shfl_xor_sync(0xffffffffu, sLo, 8);
        float gHi = sHi + __shfl_xor_sync(0xffffffffu, sHi, 8);
        s[n] = (lane & 8) ? gHi : gLo;
    }
#pragma unroll
    for (int off = 4; off > 0; off >>= 1) {
#pragma unroll
        for (int n = 0; n < 9; ++n)
            s[n] += __shfl_xor_sync(0xffffffffu, s[n], off);
    }

    float a[9], den = 0.f;
#pragma unroll
    for (int n = 0; n < 9; ++n) {
        a[n] = __expf(s[n] * scale);
        den += a[n];
    }
    float inv = 1.0f / den;

    if ((lane & 7) == 0) {
#pragma unroll
        for (int n = 0; n < 9; ++n)
            wsm[wid][q8][n] = a[n] * inv;
    }
    __syncwarp(0xffffffffu);

    float4 oA = make_float4(0.f, 0.f, 0.f, 0.f);
    float4 oB = oA, oC = oA, oD = oA;
#pragma unroll
    for (int n = 0; n < 9; ++n) {
        const int di = n / 3, dj = n % 3;
        const float wA = wsm[wid][0][n];
        const float wB = wsm[wid][1][n];
        const float wC = wsm[wid][2][n];
        const float wD = wsm[wid][3][n];
        const float4 qa = h2f4(vh[di][dj]);
        const float4 qb = h2f4(vh[di][dj + 1]);
        const float4 qc = h2f4(vh[di + 1][dj]);
        const float4 qd = h2f4(vh[di + 1][dj + 1]);
        oA.x = fmaf(wA, qa.x, oA.x); oA.y = fmaf(wA, qa.y, oA.y);
        oA.z = fmaf(wA, qa.z, oA.z); oA.w = fmaf(wA, qa.w, oA.w);
        oB.x = fmaf(wB, qb.x, oB.x); oB.y = fmaf(wB, qb.y, oB.y);
        oB.z = fmaf(wB, qb.z, oB.z); oB.w = fmaf(wB, qb.w, oB.w);
        oC.x = fmaf(wC, qc.x, oC.x); oC.y = fmaf(wC, qc.y, oC.y);
        oC.z = fmaf(wC, qc.z, oC.z); oC.w = fmaf(wC, qc.w, oC.w);
        oD.x = fmaf(wD, qd.x, oD.x); oD.y = fmaf(wD, qd.y, oD.y);
        oD.z = fmaf(wD, qd.z, oD.z); oD.w = fmaf(wD, qd.w, oD.w);
    }

    {
        const int colA = wid * 2;
        *reinterpret_cast<float4*>(&so[(0 * 16 + colA)     * CO + lane * 4]) = oA;
        *reinterpret_cast<float4*>(&so[(0 * 16 + colA + 1) * CO + lane * 4]) = oB;
        *reinterpret_cast<float4*>(&so[(1 * 16 + colA)     * CO + lane * 4]) = oC;
        *reinterpret_cast<float4*>(&so[(1 * 16 + colA + 1) * CO + lane * 4]) = oD;
    }
    __syncthreads();

    {
        const int c    = tid >> 1;
        const int part = tid & 1;
        float* dst = out + ((size_t)b * CO + c) * HW + r0 * WW + wc + part * 8;
#pragma unroll
        for (int row = 0; row < 2; ++row) {
#pragma unroll
            for (int q = 0; q < 2; ++q) {
                int col = part * 8 + q * 4;
                float4 r;
                r.x = so[(row * 16 + col + 0) * CO + c];
                r.y = so[(row * 16 + col + 1) * CO + c];
                r.z = so[(row * 16 + col + 2) * CO + c];
                r.w = so[(row * 16 + col + 3) * CO + c];
                *reinterpret_cast<float4*>(dst + row * WW + q * 4) = r;
            }
        }
    }
}

// ---------------------------------------------------------------------------
extern "C" void kernel_launch(void* const* d_in, const int* in_sizes, int n_in,
                              void* d_out, int out_size)
{
    const float* x  = nullptr;
    const float* Wc = nullptr;
    const float* bc = nullptr;
    for (int i = 0; i < n_in; ++i) {
        if (in_sizes[i] == BATCH * CI * HW) x  = (const float*)d_in[i];
        else if (in_sizes[i] == CO * CI)    Wc = (const float*)d_in[i];
        else if (in_sizes[i] == CO)         bc = (const float*)d_in[i];
    }
    float* out = (float*)d_out;

    cudaFuncSetAttribute(conv1x1_hybrid,
                         cudaFuncAttributeMaxDynamicSharedMemorySize, CONV_SMEM);

    conv1x1_hybrid<<<dim3(HW / 128, BATCH), 256, CONV_SMEM>>>(x, Wc, bc);
    attn3x3_kernel<<<dim3(WW / 16, HH / 2, BATCH), 256>>>(out);
}

// round 14
// speedup vs baseline: 1.2346x; 1.2346x over previous
#include <cuda_runtime.h>
#include <cuda_fp16.h>
#include <cstdint>

// Problem constants
#define BATCH 8
#define CI    64
#define CO    128
#define HH    128
#define WW    128
#define HW    (HH*WW)          // 16384

// Scratch: y = conv1x1(x), PIXEL-MAJOR, fp16: y[b][p][c]. 32 MiB.
__device__ __half g_y[BATCH * HW * CO];

// ---- packed f32x2 helpers (Blackwell FFMA2) --------------------------------
__device__ __forceinline__ unsigned long long pk2(float a, float b) {
    unsigned long long r;
    asm("mov.b64 %0, {%1, %2};" : "=l"(r) : "f"(a), "f"(b));
    return r;
}
__device__ __forceinline__ void fma2(unsigned long long& d,
                                     unsigned long long a,
                                     unsigned long long b) {
    asm("fma.rn.f32x2 %0, %1, %2, %0;" : "+l"(d) : "l"(a), "l"(b));
}
__device__ __forceinline__ void upk2(float& a, float& b, unsigned long long v) {
    asm("mov.b64 {%0, %1}, %2;" : "=f"(a), "=f"(b) : "l"(v));
}

// ---- fp16 helpers -----------------------------------------------------------
__device__ __forceinline__ __half2 u2h(uint32_t u) {
    return *reinterpret_cast<__half2*>(&u);
}
// fp16 4-elem dot (2 fused h2 ops), result widened to fp32
__device__ __forceinline__ float dot4h(uint2 a, uint2 b) {
    __half2 p = __hmul2(u2h(a.x), u2h(b.x));
    p = __hfma2(u2h(a.y), u2h(b.y), p);
    float2 f = __half22float2(p);
    return f.x + f.y;
}

// ---------------------------------------------------------------------------
// Kernel 1: 1x1 conv, FFMA2 GEMM (proven R12 core — at fp32 FMA wall).
// ---------------------------------------------------------------------------
__global__ void __launch_bounds__(256) conv1x1_kernel(const float* __restrict__ x,
                                                      const float* __restrict__ Wc,
                                                      const float* __restrict__ bc)
{
    extern __shared__ float sm[];
    float* Ws = sm;            // [i][o] 64*128 (Wc transposed)
    float* Xs = sm + 64 * 128; // [i][p] 64*128

    const int b   = blockIdx.y;
    const int p0  = blockIdx.x * 128;
    const int tid = threadIdx.x;

    for (int idx = tid; idx < 64 * 128; idx += 256) {
        int i = idx >> 7;
        int o = idx & 127;
        Ws[idx] = Wc[o * CI + i];
    }
    {
        const float4* xb4 = reinterpret_cast<const float4*>(x + (size_t)b * CI * HW);
        float4* Xs4 = reinterpret_cast<float4*>(Xs);
        for (int idx = tid; idx < 2048; idx += 256) {
            int i  = idx >> 5;
            int p4 = idx & 31;
            Xs4[idx] = xb4[i * (HW / 4) + (p0 >> 2) + p4];
        }
    }
    __syncthreads();

    const int tx = tid & 15;   // channel group
    const int ty = tid >> 4;   // pixel group

    unsigned long long acc2[4][8];
#pragma unroll
    for (int q = 0; q < 4; ++q)
#pragma unroll
        for (int k = 0; k < 8; ++k) acc2[q][k] = 0ull;

    const float4* Ws4 = reinterpret_cast<const float4*>(Ws);

#pragma unroll 4
    for (int i = 0; i < 64; ++i) {
        float4 w0 = Ws4[i * 32 + tx];
        float4 w1 = Ws4[i * 32 + 16 + tx];

        const float* xrow = Xs + i * 128;
        ulonglong2 xa = *reinterpret_cast<const ulonglong2*>(xrow + ty * 8);
        ulonglong2 xb = *reinterpret_cast<const ulonglong2*>(xrow + ty * 8 + 4);
        unsigned long long xp[4] = {xa.x, xa.y, xb.x, xb.y};

        unsigned long long wd[8];
        wd[0] = pk2(w0.x, w0.x); wd[1] = pk2(w0.y, w0.y);
        wd[2] = pk2(w0.z, w0.z); wd[3] = pk2(w0.w, w0.w);
        wd[4] = pk2(w1.x, w1.x); wd[5] = pk2(w1.y, w1.y);
        wd[6] = pk2(w1.z, w1.z); wd[7] = pk2(w1.w, w1.w);

#pragma unroll
        for (int q = 0; q < 4; ++q)
#pragma unroll
            for (int k = 0; k < 8; ++k)
                fma2(acc2[q][k], xp[q], wd[k]);
    }

    float bv[8];
#pragma unroll
    for (int k = 0; k < 4; ++k) {
        bv[k]     = bc[tx * 4 + k];
        bv[k + 4] = bc[64 + tx * 4 + k];
    }

    __half* yb = g_y + ((size_t)b * HW + p0) * CO;
#pragma unroll
    for (int q = 0; q < 4; ++q) {
#pragma unroll
        for (int half = 0; half < 2; ++half) {
            float e[8];
#pragma unroll
            for (int k = 0; k < 8; ++k) {
                float lo, hi;
                upk2(lo, hi, acc2[q][k]);
                e[k] = (half == 0 ? lo : hi) + bv[k];
            }
            __half* dst = yb + (size_t)(ty * 8 + q * 2 + half) * CO;
            __half2 h0 = __floats2half2_rn(e[0], e[1]);
            __half2 h1 = __floats2half2_rn(e[2], e[3]);
            __half2 h2 = __floats2half2_rn(e[4], e[5]);
            __half2 h3 = __floats2half2_rn(e[6], e[7]);
            *reinterpret_cast<uint2*>(dst + tx * 4) =
                make_uint2(*reinterpret_cast<uint32_t*>(&h0),
                           *reinterpret_cast<uint32_t*>(&h1));
            *reinterpret_cast<uint2*>(dst + 64 + tx * 4) =
                make_uint2(*reinterpret_cast<uint32_t*>(&h2),
                           *reinterpret_cast<uint32_t*>(&h3));
        }
    }
}

// ---------------------------------------------------------------------------
// Kernel 2: 3x3 local attention, warp per 2x2 pixel block, fp16 arithmetic.
// Scores: HFMA2 dots directly on fp16 regs (per-lane), fp32 reduction.
// Weighted sum: HFMA2 with half2-duplicated weights from smem.
// Softmax (exp/normalize) stays fp32. Quarter-split butterfly reduction.
// ---------------------------------------------------------------------------
__global__ void __launch_bounds__(256, 3) attn3x3_kernel(float* __restrict__ out)
{
    __shared__ float    so[32 * CO];     // [px(row*16+col)][c]  16KB
    __shared__ uint32_t wsm[8][4][12];   // [warp][pixel][9 weights as half2-dup]

    const int tid  = threadIdx.x;
    const int wid  = tid >> 5;
    const int lane = tid & 31;

    const int b  = blockIdx.z;
    const int r0 = blockIdx.y * 2;          // tile rows r0, r0+1
    const int wc = blockIdx.x * 16;         // tile cols wc..wc+15
    const int c0 = wc + wid * 2;            // this warp's 2 cols

    const __half* ybase = g_y + ((size_t)b * HW) * CO + lane * 4;

    // Load 4x4 fp16 neighborhood, KEEP fp16 in registers
    uint2 vh[4][4];
#pragma unroll
    for (int r = 0; r < 4; ++r) {
        int gh = r0 - 1 + r;
#pragma unroll
        for (int c = 0; c < 4; ++c) {
            int gw = c0 - 1 + c;
            if ((unsigned)gh < HH && (unsigned)gw < WW) {
                vh[r][c] = *reinterpret_cast<const uint2*>(
                    ybase + (size_t)(gh * WW + gw) * CO);
            } else {
                vh[r][c] = make_uint2(0u, 0u);
            }
        }
    }

    const float scale = 0.08838834764831845f; // 1/sqrt(128)
    const bool loHalf = lane < 16;
    const int  q8     = (lane >> 3) & 3;      // quarter: 0=A 1=B 2=C 3=D

    // Scores in fp16 (per-lane 4-dots), quarter-split butterfly fold
    float s[9];
#pragma unroll
    for (int n = 0; n < 9; ++n) {
        const int di = n / 3, dj = n % 3;
        float sA = dot4h(vh[di][dj],         vh[1][1]);
        float sB = dot4h(vh[di][dj + 1],     vh[1][2]);
        float sC = dot4h(vh[di + 1][dj],     vh[2][1]);
        float sD = dot4h(vh[di + 1][dj + 1], vh[2][2]);
        float fA = sA + __shfl_xor_sync(0xffffffffu, sA, 16);
        float fB = sB + __shfl_xor_sync(0xffffffffu, sB, 16);
        float fC = sC + __shfl_xor_sync(0xffffffffu, sC, 16);
        float fD = sD + __shfl_xor_sync(0xffffffffu, sD, 16);
        float sLo = loHalf ? fA : fC;
        float sHi = loHalf ? fB : fD;
        float gLo = sLo + __shfl_xor_sync(0xffffffffu, sLo, 8);
        float gHi = sHi + __shfl_xor_sync(0xffffffffu, sHi, 8);
        s[n] = (lane & 8) ? gHi : gLo;
    }
#pragma unroll
    for (int off = 4; off > 0; off >>= 1) {
#pragma unroll
        for (int n = 0; n < 9; ++n)
            s[n] += __shfl_xor_sync(0xffffffffu, s[n], off);
    }

    // Softmax fp32 for this lane's quarter-pixel (no max-sub: bounded)
    float a[9], den = 0.f;
#pragma unroll
    for (int n = 0; n < 9; ++n) {
        a[n] = __expf(s[n] * scale);
        den += a[n];
    }
    float inv = 1.0f / den;

    // Broadcast weights as half2-dup via smem (one writer lane per quarter)
    if ((lane & 7) == 0) {
#pragma unroll
        for (int n = 0; n < 9; ++n) {
            __half2 hd = __half2half2(__float2half_rn(a[n] * inv));
            wsm[wid][q8][n] = *reinterpret_cast<uint32_t*>(&hd);
        }
    }
    __syncwarp(0xffffffffu);

    // Weighted sums for all 4 pixels, fp16 HFMA2 accumulation
    __half2 accx[4], accy[4];
#pragma unroll
    for (int p = 0; p < 4; ++p) {
        accx[p] = __half2half2(__ushort_as_half(0));
        accy[p] = accx[p];
    }
#pragma unroll
    for (int n = 0; n < 9; ++n) {
        const int di = n / 3, dj = n % 3;
        const __half2 wA = u2h(wsm[wid][0][n]);
        const __half2 wB = u2h(wsm[wid][1][n]);
        const __half2 wC = u2h(wsm[wid][2][n]);
        const __half2 wD = u2h(wsm[wid][3][n]);
        const uint2 qa = vh[di][dj];
        const uint2 qb = vh[di][dj + 1];
        const uint2 qc = vh[di + 1][dj];
        const uint2 qd = vh[di + 1][dj + 1];
        accx[0] = __hfma2(wA, u2h(qa.x), accx[0]);
        accy[0] = __hfma2(wA, u2h(qa.y), accy[0]);
        accx[1] = __hfma2(wB, u2h(qb.x), accx[1]);
        accy[1] = __hfma2(wB, u2h(qb.y), accy[1]);
        accx[2] = __hfma2(wC, u2h(qc.x), accx[2]);
        accy[2] = __hfma2(wC, u2h(qc.y), accy[2]);
        accx[3] = __hfma2(wD, u2h(qd.x), accx[3]);
        accy[3] = __hfma2(wD, u2h(qd.y), accy[3]);
    }

    // Widen to fp32 and stage [px][c]
    {
        const int colA = wid * 2;
#pragma unroll
        for (int p = 0; p < 4; ++p) {
            float2 fx = __half22float2(accx[p]);
            float2 fy = __half22float2(accy[p]);
            float4 o = make_float4(fx.x, fx.y, fy.x, fy.y);
            int px = (p >> 1) * 16 + colA + (p & 1);   // A,B row0; C,D row1
            *reinterpret_cast<float4*>(&so[px * CO + lane * 4]) = o;
        }
    }
    __syncthreads();

    // Transposed, channel-major store
    {
        const int c    = tid >> 1;
        const int part = tid & 1;
        float* dst = out + ((size_t)b * CO + c) * HW + r0 * WW + wc + part * 8;
#pragma unroll
        for (int row = 0; row < 2; ++row) {
#pragma unroll
            for (int q = 0; q < 2; ++q) {
                int col = part * 8 + q * 4;
                float4 r;
                r.x = so[(row * 16 + col + 0) * CO + c];
                r.y = so[(row * 16 + col + 1) * CO + c];
                r.z = so[(row * 16 + col + 2) * CO + c];
                r.w = so[(row * 16 + col + 3) * CO + c];
                *reinterpret_cast<float4*>(dst + row * WW + q * 4) = r;
            }
        }
    }
}

// ---------------------------------------------------------------------------
extern "C" void kernel_launch(void* const* d_in, const int* in_sizes, int n_in,
                              void* d_out, int out_size)
{
    const float* x  = nullptr;
    const float* Wc = nullptr;
    const float* bc = nullptr;
    for (int i = 0; i < n_in; ++i) {
        if (in_sizes[i] == BATCH * CI * HW) x  = (const float*)d_in[i];
        else if (in_sizes[i] == CO * CI)    Wc = (const float*)d_in[i];
        else if (in_sizes[i] == CO)         bc = (const float*)d_in[i];
    }
    float* out = (float*)d_out;

    static const int conv_smem = 64 * 128 * 2 * sizeof(float);   // 65536

    cudaFuncSetAttribute(conv1x1_kernel,
                         cudaFuncAttributeMaxDynamicSharedMemorySize, conv_smem);

    conv1x1_kernel<<<dim3(HW / 128, BATCH), 256, conv_smem>>>(x, Wc, bc);
    attn3x3_kernel<<<dim3(WW / 16, HH / 2, BATCH), 256>>>(out);
}